// round 1
// baseline (speedup 1.0000x reference)
#include <cuda_runtime.h>
#include <cstdint>
#include <math.h>

#define Bsz 64
#define Tt  512
#define Din 256
#define Hs  1024
#define G4  4096
#define MROWS (Tt*Bsz)          // 32768 output rows for xg GEMMs
#define NBLK_REC 128
#define WROW 1028               // padded Whh smem row stride (floats)
#define REDSTRIDE 33

// persistent scratch (static device allocs are the sanctioned scratch path)
__device__ float g_xg[(size_t)MROWS * G4];     // [T][B][4H]
__device__ float g_seq[(size_t)MROWS * Hs];    // [T][B][H]  layer-0 outputs
__device__ float g_hbuf[2][Bsz * Hs];          // double-buffered hidden state
__device__ unsigned g_barcnt;
__device__ volatile unsigned g_bargen;

// ---------------------------------------------------------------- helpers
__device__ __forceinline__ unsigned f2tf(float f) {
    unsigned u;
    asm("cvt.rna.tf32.f32 %0, %1;" : "=r"(u) : "f"(f));
    return u;
}

__device__ __forceinline__ void mma_tf32(float* d, const unsigned* a, unsigned b0, unsigned b1) {
    asm volatile(
        "mma.sync.aligned.m16n8k8.row.col.f32.tf32.tf32.f32 "
        "{%0,%1,%2,%3},{%4,%5,%6,%7},{%8,%9},{%0,%1,%2,%3};"
        : "+f"(d[0]), "+f"(d[1]), "+f"(d[2]), "+f"(d[3])
        : "r"(a[0]), "r"(a[1]), "r"(a[2]), "r"(a[3]), "r"(b0), "r"(b1));
}

__device__ __forceinline__ float sigmoidf_(float x) {
    return 1.f / (1.f + expf(-x));
}

// grid-wide barrier; gpu-scope fences emit CCTL.IVALL -> L1D invalidated (coherent h)
__device__ __forceinline__ void grid_barrier(unsigned nblk) {
    __threadfence();            // release: all threads' prior writes ordered to L2
    __syncthreads();
    if (threadIdx.x == 0) {
        unsigned gen = g_bargen;
        if (atomicAdd(&g_barcnt, 1u) == nblk - 1u) {
            g_barcnt = 0;
            __threadfence();
            g_bargen = gen + 1u;
        } else {
            while (g_bargen == gen) __nanosleep(32);
        }
    }
    __syncthreads();
    __threadfence();            // acquire: invalidate L1 so fresh h is visible
}

// ---------------------------------------------------------------- xg GEMM
// out[r][j] = sum_k A[r][k] * W[j][k] + bias[j],  r = t*B+b  (M=32768, N=4096)
// mode 0: A row r maps to x[(b*T+t)*Din]   (K=256)
// mode 1: A row r maps to g_seq[r*Hs]      (K=1024)
__global__ __launch_bounds__(256, 2)
void gemm_xg_kernel(const float* __restrict__ A, const float* __restrict__ W,
                    const float* __restrict__ bias, int K, int mode)
{
    __shared__ unsigned As[128 * 36];
    __shared__ unsigned Bs[128 * 36];

    const int tid  = threadIdx.x;
    const int lane = tid & 31, warp = tid >> 5;
    const int gid  = lane >> 2, tig = lane & 3;
    const int wm   = warp >> 1, wn = warp & 1;     // 4x2 warp grid, warp tile 32x64
    const int bm   = blockIdx.y * 128, bn = blockIdx.x * 128;

    float acc[2][8][4] = {};

    for (int k0 = 0; k0 < K; k0 += 32) {
        // stage A tile (128 rows x 32 cols), tf32-converted
        for (int i = tid; i < 1024; i += 256) {
            int row = i >> 3, kk = (i & 7) << 2;
            int rm = bm + row;
            size_t src;
            const float* base;
            if (mode == 0) {
                int t = rm >> 6, b = rm & 63;
                src = ((size_t)(b * Tt + t)) * Din + k0 + kk;
                base = A;
            } else {
                src = (size_t)rm * Hs + k0 + kk;
                base = g_seq;
            }
            float4 v = *reinterpret_cast<const float4*>(base + src);
            uint4 u;
            u.x = f2tf(v.x); u.y = f2tf(v.y); u.z = f2tf(v.z); u.w = f2tf(v.w);
            *reinterpret_cast<uint4*>(&As[row * 36 + kk]) = u;
        }
        // stage B tile: Bs[n][k] = W[bn+n][k0+k]
        for (int i = tid; i < 1024; i += 256) {
            int row = i >> 3, kk = (i & 7) << 2;
            float4 v = *reinterpret_cast<const float4*>(W + (size_t)(bn + row) * K + k0 + kk);
            uint4 u;
            u.x = f2tf(v.x); u.y = f2tf(v.y); u.z = f2tf(v.z); u.w = f2tf(v.w);
            *reinterpret_cast<uint4*>(&Bs[row * 36 + kk]) = u;
        }
        __syncthreads();

        #pragma unroll
        for (int ks = 0; ks < 4; ++ks) {
            int kk = ks * 8;
            unsigned a[2][4];
            #pragma unroll
            for (int mt = 0; mt < 2; ++mt) {
                int m = wm * 32 + mt * 16 + gid;
                a[mt][0] = As[m * 36 + kk + tig];
                a[mt][1] = As[(m + 8) * 36 + kk + tig];
                a[mt][2] = As[m * 36 + kk + tig + 4];
                a[mt][3] = As[(m + 8) * 36 + kk + tig + 4];
            }
            #pragma unroll
            for (int nt = 0; nt < 8; ++nt) {
                int n = wn * 64 + nt * 8 + gid;
                unsigned b0 = Bs[n * 36 + kk + tig];
                unsigned b1 = Bs[n * 36 + kk + tig + 4];
                mma_tf32(acc[0][nt], a[0], b0, b1);
                mma_tf32(acc[1][nt], a[1], b0, b1);
            }
        }
        __syncthreads();
    }

    #pragma unroll
    for (int mt = 0; mt < 2; ++mt) {
        #pragma unroll
        for (int nt = 0; nt < 8; ++nt) {
            int row = bm + wm * 32 + mt * 16 + gid;
            int col = bn + wn * 64 + nt * 8 + 2 * tig;
            float bc0 = bias[col], bc1 = bias[col + 1];
            float2 v0 = make_float2(acc[mt][nt][0] + bc0, acc[mt][nt][1] + bc1);
            float2 v1 = make_float2(acc[mt][nt][2] + bc0, acc[mt][nt][3] + bc1);
            *reinterpret_cast<float2*>(&g_xg[(size_t)row * G4 + col]) = v0;
            *reinterpret_cast<float2*>(&g_xg[(size_t)(row + 8) * G4 + col]) = v1;
        }
    }
}

// ---------------------------------------------------------------- recurrent
// Persistent kernel: 128 CTAs, CTA owns 8 hidden units (32 gate columns).
// Whh slice resident in SMEM (tf32). Per step: 8-way K-split tf32 MMA of
// h[64,1024] x Whh_slice -> partials in smem -> reduce + gate nonlinearity ->
// write h (and seq for layer 0) -> grid barrier.
#define RSMEM (32*WROW*4 + 8*64*REDSTRIDE*4 + 512*4)

__global__ __launch_bounds__(256, 1)
void rec_kernel(const float* __restrict__ Whh, int write_seq)
{
    extern __shared__ unsigned char smraw[];
    unsigned* Ws = (unsigned*)smraw;                                   // [32][WROW]
    float* red   = (float*)(smraw + 32 * WROW * 4);                    // [8][64][33]
    float* csm   = (float*)(smraw + 32 * WROW * 4 + 8 * 64 * REDSTRIDE * 4); // [512]

    const int tid  = threadIdx.x;
    const int lane = tid & 31, warp = tid >> 5;
    const int gid  = lane >> 2, tig = lane & 3;
    const int u0   = blockIdx.x * 8;

    // one-time: load Whh slice (rows {g*H + u0 + n}) as tf32 bits
    for (int l = 0; l < 32; ++l) {
        int g = l >> 3, n = l & 7;
        const float* src = Whh + (size_t)(g * Hs + u0 + n) * Hs;
        for (int k = tid; k < Hs; k += 256)
            Ws[l * WROW + k] = f2tf(src[k]);
    }
    // init state: c = 0, h0 = 0
    for (int cell = tid; cell < 512; cell += 256) {
        csm[cell] = 0.f;
        int b = cell >> 3, u = cell & 7;
        g_hbuf[0][b * Hs + u0 + u] = 0.f;
    }
    grid_barrier(NBLK_REC);

    for (int t = 0; t < Tt; ++t) {
        const float* hp = g_hbuf[t & 1];
        float* hn = g_hbuf[(t + 1) & 1];

        float acc[4][4][4] = {};           // [mtile][gate-group][frag]
        const int kb = warp * 128;         // warp's K chunk

        #pragma unroll 4
        for (int ks = 0; ks < 16; ++ks) {
            int k0 = kb + ks * 8;
            unsigned a[4][4];
            #pragma unroll
            for (int mt = 0; mt < 4; ++mt) {
                int m = mt * 16 + gid;
                a[mt][0] = f2tf(hp[m * Hs + k0 + tig]);
                a[mt][1] = f2tf(hp[(m + 8) * Hs + k0 + tig]);
                a[mt][2] = f2tf(hp[m * Hs + k0 + tig + 4]);
                a[mt][3] = f2tf(hp[(m + 8) * Hs + k0 + tig + 4]);
            }
            #pragma unroll
            for (int g = 0; g < 4; ++g) {
                unsigned b0 = Ws[(g * 8 + gid) * WROW + k0 + tig];
                unsigned b1 = Ws[(g * 8 + gid) * WROW + k0 + tig + 4];
                #pragma unroll
                for (int mt = 0; mt < 4; ++mt)
                    mma_tf32(acc[mt][g], a[mt], b0, b1);
            }
        }

        // write K-partials
        #pragma unroll
        for (int mt = 0; mt < 4; ++mt) {
            #pragma unroll
            for (int g = 0; g < 4; ++g) {
                int m = mt * 16 + gid;
                int nl = g * 8 + 2 * tig;
                float* r0 = red + (warp * 64 + m) * REDSTRIDE;
                float* r1 = red + (warp * 64 + m + 8) * REDSTRIDE;
                r0[nl] = acc[mt][g][0]; r0[nl + 1] = acc[mt][g][1];
                r1[nl] = acc[mt][g][2]; r1[nl + 1] = acc[mt][g][3];
            }
        }
        __syncthreads();

        // reduce partials + gate nonlinearities + state update
        #pragma unroll
        for (int it = 0; it < 2; ++it) {
            int cell = tid + it * 256;     // 0..511
            int b = cell >> 3, u = cell & 7;
            float gi = 0.f, gf = 0.f, gg = 0.f, go = 0.f;
            #pragma unroll
            for (int w = 0; w < 8; ++w) {
                const float* r = red + (w * 64 + b) * REDSTRIDE;
                gi += r[u];
                gf += r[8 + u];
                gg += r[16 + u];
                go += r[24 + u];
            }
            size_t xb = ((size_t)t * Bsz + b) * (size_t)G4 + u0 + u;
            gi += g_xg[xb];
            gf += g_xg[xb + Hs];
            gg += g_xg[xb + 2 * Hs];
            go += g_xg[xb + 3 * Hs];

            gi = sigmoidf_(gi);
            gf = sigmoidf_(gf);
            gg = tanhf(gg);
            go = sigmoidf_(go);

            float c = gf * csm[cell] + gi * gg;
            csm[cell] = c;
            float h = go * tanhf(c);
            hn[b * Hs + u0 + u] = h;
            if (write_seq)
                g_seq[((size_t)t * Bsz + b) * Hs + u0 + u] = h;
        }
        grid_barrier(NBLK_REC);
    }
}

// ---------------------------------------------------------------- final FC
__global__ void fc_kernel(const float* __restrict__ Wfc, const float* __restrict__ bfc,
                          float* __restrict__ out)
{
    int b = blockIdx.x;
    const float* h = g_hbuf[0] + b * Hs;   // layer-1 final hidden (t=511 wrote buf 0)
    float s = 0.f;
    for (int k = threadIdx.x; k < Hs; k += 128)
        s += h[k] * Wfc[k];
    #pragma unroll
    for (int o = 16; o > 0; o >>= 1)
        s += __shfl_down_sync(0xffffffffu, s, o);
    __shared__ float sm[4];
    if ((threadIdx.x & 31) == 0) sm[threadIdx.x >> 5] = s;
    __syncthreads();
    if (threadIdx.x == 0)
        out[b] = sm[0] + sm[1] + sm[2] + sm[3] + bfc[0];
}

// ---------------------------------------------------------------- launch
extern "C" void kernel_launch(void* const* d_in, const int* in_sizes, int n_in,
                              void* d_out, int out_size)
{
    (void)in_sizes; (void)n_in; (void)out_size;
    const float* x    = (const float*)d_in[0];
    const float* Wih0 = (const float*)d_in[1];
    const float* Whh0 = (const float*)d_in[2];
    const float* b0   = (const float*)d_in[3];
    const float* Wih1 = (const float*)d_in[4];
    const float* Whh1 = (const float*)d_in[5];
    const float* b1   = (const float*)d_in[6];
    const float* Wfc  = (const float*)d_in[7];
    const float* bfc  = (const float*)d_in[8];
    float* out = (float*)d_out;

    cudaFuncSetAttribute(rec_kernel, cudaFuncAttributeMaxDynamicSharedMemorySize, RSMEM);

    dim3 grid(G4 / 128, MROWS / 128);   // (32, 256)
    gemm_xg_kernel<<<grid, 256>>>(x, Wih0, b0, Din, 0);
    rec_kernel<<<NBLK_REC, 256, RSMEM>>>(Whh0, 1);
    gemm_xg_kernel<<<grid, 256>>>(nullptr, Wih1, b1, Hs, 1);
    rec_kernel<<<NBLK_REC, 256, RSMEM>>>(Whh1, 0);
    fc_kernel<<<Bsz, 128>>>(Wfc, bfc, out);
}

// round 3
// speedup vs baseline: 1.1282x; 1.1282x over previous
#include <cuda_runtime.h>
#include <cstdint>
#include <math.h>

#define Bsz 64
#define Tt  512
#define Din 256
#define Hs  1024
#define G4  4096
#define MROWS (Tt*Bsz)
#define NBLK_REC 128
#define WROW 1028               // padded Whh smem row stride (floats)
#define REDSTRIDE 34            // even -> 8B-aligned float2 stores
#define GS 3                    // gemm pipeline stages

// persistent scratch
__device__ float g_xg[(size_t)MROWS * G4];     // [T][B][4H]
__device__ float g_seq[(size_t)MROWS * Hs];    // [T][B][H] layer-0 out (tf32-rounded)
__device__ float g_hbuf[2][Bsz * Hs];          // hidden state (tf32-rounded)
__device__ float g_xr[(size_t)Bsz * Tt * Din]; // x pre-rounded to tf32
__device__ float g_w0r[(size_t)G4 * Din];      // Wih0 pre-rounded
__device__ float g_w1r[(size_t)G4 * Hs];       // Wih1 pre-rounded
__device__ unsigned g_barcnt;
__device__ volatile unsigned g_bargen;

// ---------------------------------------------------------------- helpers
__device__ __forceinline__ unsigned f2tf(float f) {
    unsigned u;
    asm("cvt.rna.tf32.f32 %0, %1;" : "=r"(u) : "f"(f));
    return u;
}

__device__ __forceinline__ void mma_tf32(float* d, const unsigned* a, unsigned b0, unsigned b1) {
    asm volatile(
        "mma.sync.aligned.m16n8k8.row.col.f32.tf32.tf32.f32 "
        "{%0,%1,%2,%3},{%4,%5,%6,%7},{%8,%9},{%0,%1,%2,%3};"
        : "+f"(d[0]), "+f"(d[1]), "+f"(d[2]), "+f"(d[3])
        : "r"(a[0]), "r"(a[1]), "r"(a[2]), "r"(a[3]), "r"(b0), "r"(b1));
}

__device__ __forceinline__ void cp16(unsigned saddr, const void* g) {
    asm volatile("cp.async.cg.shared.global [%0], [%1], 16;" :: "r"(saddr), "l"(g));
}

__device__ __forceinline__ float sigmoidf_(float x) {
    return 1.f / (1.f + expf(-x));
}

__device__ __forceinline__ void grid_barrier(unsigned nblk) {
    __threadfence();
    __syncthreads();
    if (threadIdx.x == 0) {
        unsigned gen = g_bargen;
        if (atomicAdd(&g_barcnt, 1u) == nblk - 1u) {
            g_barcnt = 0;
            __threadfence();
            g_bargen = gen + 1u;
        } else {
            while (g_bargen == gen) __nanosleep(32);
        }
    }
    __syncthreads();
    __threadfence();
}

// ---------------------------------------------------------------- tf32 pre-round
__global__ void round_tf32_kernel(const float* __restrict__ src, float* __restrict__ dst, int n)
{
    for (int i = blockIdx.x * blockDim.x + threadIdx.x; i < n; i += gridDim.x * blockDim.x)
        ((unsigned*)dst)[i] = f2tf(src[i]);
}

// ---------------------------------------------------------------- xg GEMM
// out[r][j] = sum_k A[r][k]*W[j][k] + bias[j]; r = t*B+b. 3-stage cp.async pipeline.
// All operands already tf32-rounded -> stage raw bits, no cvt in hot path.
#define GSMEM (GS * 4608 * 2 * 4)

__global__ __launch_bounds__(256, 2)
void gemm_xg_kernel(const float* __restrict__ A, const float* __restrict__ W,
                    const float* __restrict__ bias, int K, int mode)
{
    extern __shared__ unsigned gsm[];
    unsigned* As = gsm;               // [GS][128*36]
    unsigned* Bs = gsm + GS * 4608;

    const int tid  = threadIdx.x;
    const int lane = tid & 31, warp = tid >> 5;
    const int gid  = lane >> 2, tig = lane & 3;
    const int wm   = warp >> 1, wn = warp & 1;
    const int bm   = blockIdx.y * 128, bn = blockIdx.x * 128;

    const float* ga[4]; const float* gb[4]; int soff[4];
    #pragma unroll
    for (int j = 0; j < 4; ++j) {
        int i = tid + j * 256;
        int row = i >> 3, kk = (i & 7) << 2;
        int rm = bm + row;
        if (mode)
            ga[j] = g_seq + (size_t)rm * Hs + kk;
        else
            ga[j] = A + ((size_t)(rm & 63) * Tt + (rm >> 6)) * Din + kk;
        gb[j] = W + (size_t)(bn + row) * K + kk;
        soff[j] = row * 36 + kk;
    }
    unsigned sA = (unsigned)__cvta_generic_to_shared(As);
    unsigned sB = (unsigned)__cvta_generic_to_shared(Bs);

    const int nch = K / 32;

    auto stage = [&](int s, int k0) {
        #pragma unroll
        for (int j = 0; j < 4; ++j) {
            cp16(sA + (s * 4608 + soff[j]) * 4, ga[j] + k0);
            cp16(sB + (s * 4608 + soff[j]) * 4, gb[j] + k0);
        }
        asm volatile("cp.async.commit_group;");
    };

    stage(0, 0);
    stage(1, 32);

    float acc[2][8][4] = {};

    for (int c = 0; c < nch; ++c) {
        if (c + 1 < nch) asm volatile("cp.async.wait_group 1;");
        else             asm volatile("cp.async.wait_group 0;");
        __syncthreads();
        if (c + 2 < nch) stage((c + 2) % GS, (c + 2) * 32);

        const unsigned* Asl = As + (c % GS) * 4608;
        const unsigned* Bsl = Bs + (c % GS) * 4608;
        #pragma unroll
        for (int ks = 0; ks < 4; ++ks) {
            int kk = ks * 8;
            unsigned a[2][4];
            #pragma unroll
            for (int mt = 0; mt < 2; ++mt) {
                int m = wm * 32 + mt * 16 + gid;
                a[mt][0] = Asl[m * 36 + kk + tig];
                a[mt][1] = Asl[(m + 8) * 36 + kk + tig];
                a[mt][2] = Asl[m * 36 + kk + tig + 4];
                a[mt][3] = Asl[(m + 8) * 36 + kk + tig + 4];
            }
            #pragma unroll
            for (int nt = 0; nt < 8; ++nt) {
                int n = wn * 64 + nt * 8 + gid;
                unsigned b0 = Bsl[n * 36 + kk + tig];
                unsigned b1 = Bsl[n * 36 + kk + tig + 4];
                mma_tf32(acc[0][nt], a[0], b0, b1);
                mma_tf32(acc[1][nt], a[1], b0, b1);
            }
        }
    }

    #pragma unroll
    for (int mt = 0; mt < 2; ++mt) {
        #pragma unroll
        for (int nt = 0; nt < 8; ++nt) {
            int row = bm + wm * 32 + mt * 16 + gid;
            int col = bn + wn * 64 + nt * 8 + 2 * tig;
            float bc0 = bias[col], bc1 = bias[col + 1];
            float2 v0 = make_float2(acc[mt][nt][0] + bc0, acc[mt][nt][1] + bc1);
            float2 v1 = make_float2(acc[mt][nt][2] + bc0, acc[mt][nt][3] + bc1);
            *reinterpret_cast<float2*>(&g_xg[(size_t)row * G4 + col]) = v0;
            *reinterpret_cast<float2*>(&g_xg[(size_t)(row + 8) * G4 + col]) = v1;
        }
    }
}

// ---------------------------------------------------------------- recurrent
// 128 persistent CTAs, 8 hidden units each (32 gate cols). Warps: 4 M-tiles x 2 K-slices.
// h stored tf32-rounded -> zero cvt in hot loop. xg prefetched before MMA.
#define RSMEM (32*WROW*4 + 2*64*REDSTRIDE*4 + 512*4)

__global__ __launch_bounds__(256, 1)
void rec_kernel(const float* __restrict__ Whh, int write_seq)
{
    extern __shared__ unsigned char smraw[];
    unsigned* Ws = (unsigned*)smraw;                                  // [32][WROW]
    float* red   = (float*)(smraw + 32 * WROW * 4);                   // [2][64][34]
    float* csm   = (float*)(smraw + 32 * WROW * 4 + 2 * 64 * REDSTRIDE * 4);

    const int tid  = threadIdx.x;
    const int lane = tid & 31, warp = tid >> 5;
    const int gid  = lane >> 2, tig = lane & 3;
    const int u0   = blockIdx.x * 8;
    const int mrow = (warp & 3) * 16;       // 16 batch rows per warp
    const int ksl  = warp >> 2;             // 2-way K split
    const int kbase = ksl * 512;

    for (int l = 0; l < 32; ++l) {
        int g = l >> 3, n = l & 7;
        const float* src = Whh + (size_t)(g * Hs + u0 + n) * Hs;
        for (int k = tid; k < Hs; k += 256)
            Ws[l * WROW + k] = f2tf(src[k]);
    }
    for (int cell = tid; cell < 512; cell += 256) {
        csm[cell] = 0.f;
        int b = cell >> 3, u = cell & 7;
        g_hbuf[0][b * Hs + u0 + u] = 0.f;
    }
    grid_barrier(NBLK_REC);

    const int bb = tid >> 3, uu = tid & 7;

    for (int t = 0; t < Tt; ++t) {
        const unsigned* hp = (const unsigned*)g_hbuf[t & 1];
        float* hn = g_hbuf[(t + 1) & 1];

        // prefetch this step's xg contributions (DRAM latency hidden behind MMA)
        float px[2][4];
        #pragma unroll
        for (int it = 0; it < 2; ++it) {
            int b = bb + it * 32;
            size_t xb = ((size_t)t * Bsz + b) * (size_t)G4 + u0 + uu;
            px[it][0] = g_xg[xb];
            px[it][1] = g_xg[xb + Hs];
            px[it][2] = g_xg[xb + 2 * Hs];
            px[it][3] = g_xg[xb + 3 * Hs];
        }

        float acc[4][4] = {};
        const unsigned* hr0 = hp + (mrow + gid) * Hs + kbase + tig;
        const unsigned* hr1 = hp + (mrow + gid + 8) * Hs + kbase + tig;

        #pragma unroll 8
        for (int ks = 0; ks < 64; ++ks) {
            int k8 = ks * 8;
            unsigned a[4] = { hr0[k8], hr1[k8], hr0[k8 + 4], hr1[k8 + 4] };
            int kw = kbase + k8 + tig;
            #pragma unroll
            for (int g = 0; g < 4; ++g) {
                unsigned b0 = Ws[(g * 8 + gid) * WROW + kw];
                unsigned b1 = Ws[(g * 8 + gid) * WROW + kw + 4];
                mma_tf32(acc[g], a, b0, b1);
            }
        }

        #pragma unroll
        for (int g = 0; g < 4; ++g) {
            float* r0 = red + (size_t)(ksl * 64 + mrow + gid) * REDSTRIDE + g * 8 + 2 * tig;
            float* r1 = r0 + 8 * REDSTRIDE;
            *reinterpret_cast<float2*>(r0) = make_float2(acc[g][0], acc[g][1]);
            *reinterpret_cast<float2*>(r1) = make_float2(acc[g][2], acc[g][3]);
        }
        __syncthreads();

        #pragma unroll
        for (int it = 0; it < 2; ++it) {
            int cell = tid + it * 256;
            int b = cell >> 3, u = cell & 7;
            const float* ra = red + (size_t)b * REDSTRIDE;
            const float* rb = ra + 64 * REDSTRIDE;
            float gi = ra[u]      + rb[u]      + px[it][0];
            float gf = ra[u + 8]  + rb[u + 8]  + px[it][1];
            float gg = ra[u + 16] + rb[u + 16] + px[it][2];
            float go = ra[u + 24] + rb[u + 24] + px[it][3];

            gi = sigmoidf_(gi);
            gf = sigmoidf_(gf);
            gg = tanhf(gg);
            go = sigmoidf_(go);

            float c = gf * csm[cell] + gi * gg;
            csm[cell] = c;
            float h = go * tanhf(c);
            unsigned hb = f2tf(h);                       // store tf32-rounded
            ((unsigned*)hn)[b * Hs + u0 + u] = hb;
            if (write_seq)
                ((unsigned*)g_seq)[((size_t)t * Bsz + b) * Hs + u0 + u] = hb;
        }
        grid_barrier(NBLK_REC);
    }
}

// ---------------------------------------------------------------- final FC
__global__ void fc_kernel(const float* __restrict__ Wfc, const float* __restrict__ bfc,
                          float* __restrict__ out)
{
    int b = blockIdx.x;
    const float* h = g_hbuf[0] + b * Hs;
    float s = 0.f;
    for (int k = threadIdx.x; k < Hs; k += 128)
        s += h[k] * Wfc[k];
    #pragma unroll
    for (int o = 16; o > 0; o >>= 1)
        s += __shfl_down_sync(0xffffffffu, s, o);
    __shared__ float sm[4];
    if ((threadIdx.x & 31) == 0) sm[threadIdx.x >> 5] = s;
    __syncthreads();
    if (threadIdx.x == 0)
        out[b] = sm[0] + sm[1] + sm[2] + sm[3] + bfc[0];
}

// ---------------------------------------------------------------- launch
extern "C" void kernel_launch(void* const* d_in, const int* in_sizes, int n_in,
                              void* d_out, int out_size)
{
    (void)in_sizes; (void)n_in; (void)out_size;
    const float* x    = (const float*)d_in[0];
    const float* Wih0 = (const float*)d_in[1];
    const float* Whh0 = (const float*)d_in[2];
    const float* b0   = (const float*)d_in[3];
    const float* Wih1 = (const float*)d_in[4];
    const float* Whh1 = (const float*)d_in[5];
    const float* b1   = (const float*)d_in[6];
    const float* Wfc  = (const float*)d_in[7];
    const float* bfc  = (const float*)d_in[8];
    float* out = (float*)d_out;

    cudaFuncSetAttribute(rec_kernel, cudaFuncAttributeMaxDynamicSharedMemorySize, RSMEM);
    cudaFuncSetAttribute(gemm_xg_kernel, cudaFuncAttributeMaxDynamicSharedMemorySize, GSMEM);

    float* xr  = nullptr; cudaGetSymbolAddress((void**)&xr,  g_xr);
    float* w0r = nullptr; cudaGetSymbolAddress((void**)&w0r, g_w0r);
    float* w1r = nullptr; cudaGetSymbolAddress((void**)&w1r, g_w1r);

    round_tf32_kernel<<<4096, 256>>>(x,    xr,  Bsz * Tt * Din);
    round_tf32_kernel<<<1024, 256>>>(Wih0, w0r, G4 * Din);
    round_tf32_kernel<<<4096, 256>>>(Wih1, w1r, G4 * Hs);

    dim3 grid(G4 / 128, MROWS / 128);   // (32, 256)
    gemm_xg_kernel<<<grid, 256, GSMEM>>>(xr, w0r, b0, Din, 0);
    rec_kernel<<<NBLK_REC, 256, RSMEM>>>(Whh0, 1);
    gemm_xg_kernel<<<grid, 256, GSMEM>>>(nullptr, w1r, b1, Hs, 1);
    rec_kernel<<<NBLK_REC, 256, RSMEM>>>(Whh1, 0);
    fc_kernel<<<Bsz, 128>>>(Wfc, bfc, out);
}

// round 4
// speedup vs baseline: 1.8466x; 1.6367x over previous
#include <cuda_runtime.h>
#include <cuda_fp16.h>
#include <cstdint>
#include <math.h>

#define Bsz 64
#define Tt  512
#define Din 256
#define Hs  1024
#define G4  4096
#define MROWS (Tt*Bsz)
#define NBLK_REC 128
#define WROWH 1032              // padded Whh smem row stride (halves)
#define REDSTRIDE 34
#define GS 3
#define GSTRIDE 40              // gemm smem row stride (halves)
#define STAGEH (128*GSTRIDE)    // halves per matrix per stage

// persistent scratch
__device__ float  g_xg[(size_t)MROWS * G4];      // [T][B][4H] fp32
__device__ __half g_seqh[(size_t)MROWS * Hs];    // layer-0 outputs, fp16
__device__ __half g_hbufh[2][Bsz * Hs];          // hidden state, fp16
__device__ __half g_xh[(size_t)Bsz * Tt * Din];  // x in fp16
__device__ __half g_w0h[(size_t)G4 * Din];       // Wih0 fp16
__device__ __half g_w1h[(size_t)G4 * Hs];        // Wih1 fp16
__device__ unsigned g_barcnt;
__device__ unsigned g_bargen;

// ---------------------------------------------------------------- helpers
__device__ __forceinline__ void mma_f16(float* d, const unsigned* a, unsigned b0, unsigned b1) {
    asm volatile(
        "mma.sync.aligned.m16n8k16.row.col.f32.f16.f16.f32 "
        "{%0,%1,%2,%3},{%4,%5,%6,%7},{%8,%9},{%0,%1,%2,%3};"
        : "+f"(d[0]), "+f"(d[1]), "+f"(d[2]), "+f"(d[3])
        : "r"(a[0]), "r"(a[1]), "r"(a[2]), "r"(a[3]), "r"(b0), "r"(b1));
}

__device__ __forceinline__ void cp16(unsigned saddr, const void* g) {
    asm volatile("cp.async.cg.shared.global [%0], [%1], 16;" :: "r"(saddr), "l"(g));
}

__device__ __forceinline__ float sigmoidf_(float x) {
    return 1.f / (1.f + expf(-x));
}

// CG-style grid barrier: one fence + relaxed atom + acquire poll. No nanosleep.
__device__ __forceinline__ void grid_barrier(unsigned nblk) {
    __syncthreads();
    if (threadIdx.x == 0) {
        asm volatile("fence.acq_rel.gpu;" ::: "memory");
        unsigned gen;
        asm volatile("ld.relaxed.gpu.global.u32 %0, [%1];" : "=r"(gen) : "l"(&g_bargen));
        if (atomicAdd(&g_barcnt, 1u) == nblk - 1u) {
            g_barcnt = 0;
            asm volatile("st.release.gpu.global.u32 [%0], %1;" :: "l"(&g_bargen), "r"(gen + 1u) : "memory");
        } else {
            unsigned cur;
            do {
                asm volatile("ld.acquire.gpu.global.u32 %0, [%1];" : "=r"(cur) : "l"(&g_bargen) : "memory");
            } while (cur == gen);
        }
    }
    __syncthreads();
}

// ---------------------------------------------------------------- fp32 -> fp16
__global__ void tohalf_kernel(const float* __restrict__ src, __half* __restrict__ dst, int n)
{
    for (int i = blockIdx.x * blockDim.x + threadIdx.x; i < n; i += gridDim.x * blockDim.x)
        dst[i] = __float2half_rn(src[i]);
}

// ---------------------------------------------------------------- xg GEMM (fp16)
// out[r][j] = sum_k A[r][k]*W[j][k] + bias[j]; r = t*B+b. 3-stage cp.async pipeline.
#define GSMEM (GS * STAGEH * 2 * 2)   // bytes

__global__ __launch_bounds__(256, 2)
void gemm_xg_kernel(const __half* __restrict__ A, const __half* __restrict__ W,
                    const float* __restrict__ bias, int K, int mode)
{
    extern __shared__ __half gsm[];
    __half* As = gsm;                   // [GS][128][GSTRIDE]
    __half* Bs = gsm + GS * STAGEH;

    const int tid  = threadIdx.x;
    const int lane = tid & 31, warp = tid >> 5;
    const int gid  = lane >> 2, tig = lane & 3;
    const int wm   = warp >> 1, wn = warp & 1;
    const int bm   = blockIdx.y * 128, bn = blockIdx.x * 128;

    // each thread stages 2 A segs + 2 B segs per k32-chunk (16B each)
    const __half* ga[2]; const __half* gb[2]; int soff[2];
    #pragma unroll
    for (int j = 0; j < 2; ++j) {
        int i = tid + j * 256;          // 0..511
        int row = i >> 2, seg = (i & 3) * 8;
        int rm = bm + row;
        if (mode)
            ga[j] = g_seqh + (size_t)rm * Hs + seg;
        else
            ga[j] = A + ((size_t)(rm & 63) * Tt + (rm >> 6)) * Din + seg;
        gb[j] = W + (size_t)(bn + row) * K + seg;
        soff[j] = row * GSTRIDE + seg;
    }
    unsigned sA = (unsigned)__cvta_generic_to_shared(As);
    unsigned sB = (unsigned)__cvta_generic_to_shared(Bs);

    const int nch = K / 32;

    auto stage = [&](int s, int k0) {
        #pragma unroll
        for (int j = 0; j < 2; ++j) {
            cp16(sA + (s * STAGEH + soff[j]) * 2, ga[j] + k0);
            cp16(sB + (s * STAGEH + soff[j]) * 2, gb[j] + k0);
        }
        asm volatile("cp.async.commit_group;");
    };

    stage(0, 0);
    stage(1, 32);

    float acc[2][8][4] = {};

    for (int c = 0; c < nch; ++c) {
        if (c + 1 < nch) asm volatile("cp.async.wait_group 1;");
        else             asm volatile("cp.async.wait_group 0;");
        __syncthreads();
        if (c + 2 < nch) stage((c + 2) % GS, (c + 2) * 32);

        const __half* Asl = As + (c % GS) * STAGEH;
        const __half* Bsl = Bs + (c % GS) * STAGEH;
        #pragma unroll
        for (int s = 0; s < 2; ++s) {
            int kk = s * 16;
            unsigned a[2][4];
            #pragma unroll
            for (int mt = 0; mt < 2; ++mt) {
                int m = wm * 32 + mt * 16 + gid;
                a[mt][0] = *(const unsigned*)&Asl[m * GSTRIDE + kk + 2 * tig];
                a[mt][1] = *(const unsigned*)&Asl[(m + 8) * GSTRIDE + kk + 2 * tig];
                a[mt][2] = *(const unsigned*)&Asl[m * GSTRIDE + kk + 8 + 2 * tig];
                a[mt][3] = *(const unsigned*)&Asl[(m + 8) * GSTRIDE + kk + 8 + 2 * tig];
            }
            #pragma unroll
            for (int nt = 0; nt < 8; ++nt) {
                int n = wn * 64 + nt * 8 + gid;
                unsigned b0 = *(const unsigned*)&Bsl[n * GSTRIDE + kk + 2 * tig];
                unsigned b1 = *(const unsigned*)&Bsl[n * GSTRIDE + kk + 8 + 2 * tig];
                mma_f16(acc[0][nt], a[0], b0, b1);
                mma_f16(acc[1][nt], a[1], b0, b1);
            }
        }
    }

    #pragma unroll
    for (int mt = 0; mt < 2; ++mt) {
        #pragma unroll
        for (int nt = 0; nt < 8; ++nt) {
            int row = bm + wm * 32 + mt * 16 + gid;
            int col = bn + wn * 64 + nt * 8 + 2 * tig;
            float bc0 = bias[col], bc1 = bias[col + 1];
            float2 v0 = make_float2(acc[mt][nt][0] + bc0, acc[mt][nt][1] + bc1);
            float2 v1 = make_float2(acc[mt][nt][2] + bc0, acc[mt][nt][3] + bc1);
            *reinterpret_cast<float2*>(&g_xg[(size_t)row * G4 + col]) = v0;
            *reinterpret_cast<float2*>(&g_xg[(size_t)(row + 8) * G4 + col]) = v1;
        }
    }
}

// ---------------------------------------------------------------- recurrent (fp16 MMA)
// 128 persistent CTAs, 8 hidden units each (32 gate cols). Warps: 4 M-tiles x 2 K-slices.
#define RSMEM (32*WROWH*2 + 2*64*REDSTRIDE*4 + 512*4)

__global__ __launch_bounds__(256, 1)
void rec_kernel(const float* __restrict__ Whh, int write_seq)
{
    extern __shared__ unsigned char smraw[];
    __half* Ws = (__half*)smraw;                                       // [32][WROWH]
    float* red = (float*)(smraw + 32 * WROWH * 2);                     // [2][64][34]
    float* csm = (float*)(smraw + 32 * WROWH * 2 + 2 * 64 * REDSTRIDE * 4);

    const int tid  = threadIdx.x;
    const int lane = tid & 31, warp = tid >> 5;
    const int gid  = lane >> 2, tig = lane & 3;
    const int u0   = blockIdx.x * 8;
    const int mrow = (warp & 3) * 16;       // 16 batch rows per warp
    const int ksl  = warp >> 2;             // 2-way K split
    const int kbase = ksl * 512;

    // one-time: Whh slice -> smem fp16
    for (int l = 0; l < 32; ++l) {
        int g = l >> 3, n = l & 7;
        const float* src = Whh + (size_t)(g * Hs + u0 + n) * Hs;
        for (int k = tid; k < Hs; k += 256)
            Ws[l * WROWH + k] = __float2half_rn(src[k]);
    }
    for (int cell = tid; cell < 512; cell += 256) {
        csm[cell] = 0.f;
        int b = cell >> 3, u = cell & 7;
        g_hbufh[0][b * Hs + u0 + u] = __float2half_rn(0.f);
    }
    grid_barrier(NBLK_REC);

    const int bb = tid >> 3, uu = tid & 7;

    for (int t = 0; t < Tt; ++t) {
        const __half* hp = g_hbufh[t & 1];
        __half* hn = g_hbufh[(t + 1) & 1];

        // prefetch this step's xg contributions
        float px[2][4];
        #pragma unroll
        for (int it = 0; it < 2; ++it) {
            int b = bb + it * 32;
            size_t xb = ((size_t)t * Bsz + b) * (size_t)G4 + u0 + uu;
            px[it][0] = g_xg[xb];
            px[it][1] = g_xg[xb + Hs];
            px[it][2] = g_xg[xb + 2 * Hs];
            px[it][3] = g_xg[xb + 3 * Hs];
        }

        float acc[4][4] = {};
        const __half* hr0 = hp + (mrow + gid) * Hs + kbase + 2 * tig;
        const __half* hr1 = hr0 + 8 * Hs;

        #pragma unroll 8
        for (int ks = 0; ks < 32; ++ks) {
            int k16 = ks * 16;
            unsigned a[4];
            a[0] = *(const unsigned*)(hr0 + k16);
            a[1] = *(const unsigned*)(hr1 + k16);
            a[2] = *(const unsigned*)(hr0 + k16 + 8);
            a[3] = *(const unsigned*)(hr1 + k16 + 8);
            int kw = kbase + k16 + 2 * tig;
            #pragma unroll
            for (int g = 0; g < 4; ++g) {
                const __half* wrow = Ws + (g * 8 + gid) * WROWH + kw;
                unsigned b0 = *(const unsigned*)(wrow);
                unsigned b1 = *(const unsigned*)(wrow + 8);
                mma_f16(acc[g], a, b0, b1);
            }
        }

        #pragma unroll
        for (int g = 0; g < 4; ++g) {
            float* r0 = red + (size_t)(ksl * 64 + mrow + gid) * REDSTRIDE + g * 8 + 2 * tig;
            float* r1 = r0 + 8 * REDSTRIDE;
            *reinterpret_cast<float2*>(r0) = make_float2(acc[g][0], acc[g][1]);
            *reinterpret_cast<float2*>(r1) = make_float2(acc[g][2], acc[g][3]);
        }
        __syncthreads();

        #pragma unroll
        for (int it = 0; it < 2; ++it) {
            int cell = tid + it * 256;
            int b = cell >> 3, u = cell & 7;
            const float* ra = red + (size_t)b * REDSTRIDE;
            const float* rb = ra + 64 * REDSTRIDE;
            float gi = ra[u]      + rb[u]      + px[it][0];
            float gf = ra[u + 8]  + rb[u + 8]  + px[it][1];
            float gg = ra[u + 16] + rb[u + 16] + px[it][2];
            float go = ra[u + 24] + rb[u + 24] + px[it][3];

            gi = sigmoidf_(gi);
            gf = sigmoidf_(gf);
            gg = tanhf(gg);
            go = sigmoidf_(go);

            float c = gf * csm[cell] + gi * gg;
            csm[cell] = c;
            __half h = __float2half_rn(go * tanhf(c));
            hn[b * Hs + u0 + u] = h;
            if (write_seq)
                g_seqh[((size_t)t * Bsz + b) * Hs + u0 + u] = h;
        }
        grid_barrier(NBLK_REC);
    }
}

// ---------------------------------------------------------------- final FC
__global__ void fc_kernel(const float* __restrict__ Wfc, const float* __restrict__ bfc,
                          float* __restrict__ out)
{
    int b = blockIdx.x;
    const __half* h = g_hbufh[0] + b * Hs;
    float s = 0.f;
    for (int k = threadIdx.x; k < Hs; k += 128)
        s += __half2float(h[k]) * Wfc[k];
    #pragma unroll
    for (int o = 16; o > 0; o >>= 1)
        s += __shfl_down_sync(0xffffffffu, s, o);
    __shared__ float sm[4];
    if ((threadIdx.x & 31) == 0) sm[threadIdx.x >> 5] = s;
    __syncthreads();
    if (threadIdx.x == 0)
        out[b] = sm[0] + sm[1] + sm[2] + sm[3] + bfc[0];
}

// ---------------------------------------------------------------- launch
extern "C" void kernel_launch(void* const* d_in, const int* in_sizes, int n_in,
                              void* d_out, int out_size)
{
    (void)in_sizes; (void)n_in; (void)out_size;
    const float* x    = (const float*)d_in[0];
    const float* Wih0 = (const float*)d_in[1];
    const float* Whh0 = (const float*)d_in[2];
    const float* b0   = (const float*)d_in[3];
    const float* Wih1 = (const float*)d_in[4];
    const float* Whh1 = (const float*)d_in[5];
    const float* b1   = (const float*)d_in[6];
    const float* Wfc  = (const float*)d_in[7];
    const float* bfc  = (const float*)d_in[8];
    float* out = (float*)d_out;

    cudaFuncSetAttribute(rec_kernel, cudaFuncAttributeMaxDynamicSharedMemorySize, RSMEM);
    cudaFuncSetAttribute(gemm_xg_kernel, cudaFuncAttributeMaxDynamicSharedMemorySize, GSMEM);

    __half* xh  = nullptr; cudaGetSymbolAddress((void**)&xh,  g_xh);
    __half* w0h = nullptr; cudaGetSymbolAddress((void**)&w0h, g_w0h);
    __half* w1h = nullptr; cudaGetSymbolAddress((void**)&w1h, g_w1h);

    tohalf_kernel<<<4096, 256>>>(x,    xh,  Bsz * Tt * Din);
    tohalf_kernel<<<1024, 256>>>(Wih0, w0h, G4 * Din);
    tohalf_kernel<<<4096, 256>>>(Wih1, w1h, G4 * Hs);

    dim3 grid(G4 / 128, MROWS / 128);   // (32, 256)
    gemm_xg_kernel<<<grid, 256, GSMEM>>>(xh, w0h, b0, Din, 0);
    rec_kernel<<<NBLK_REC, 256, RSMEM>>>(Whh0, 1);
    gemm_xg_kernel<<<grid, 256, GSMEM>>>(nullptr, w1h, b1, Hs, 1);
    rec_kernel<<<NBLK_REC, 256, RSMEM>>>(Whh1, 0);
    fc_kernel<<<Bsz, 128>>>(Wfc, bfc, out);
}

// round 5
// speedup vs baseline: 2.1723x; 1.1764x over previous
#include <cuda_runtime.h>
#include <cuda_fp16.h>
#include <cstdint>
#include <math.h>

#define Bsz 64
#define Tt  512
#define Din 256
#define Hs  1024
#define G4  4096
#define MROWS (Tt*Bsz)
#define NBLK_REC 128
#define WSROW 1032              // padded weight smem row stride (halves)
#define REDSTRIDE 34
#define GS 3
#define GSTRIDE 40              // gemm smem row stride (halves)
#define STAGEH (128*GSTRIDE)

// persistent scratch
__device__ __half g_xgh[(size_t)MROWS * G4];     // [T][B][4H] layer-0 input gates, fp16
__device__ __half g_h0buf[2][Bsz * Hs];          // layer-0 hidden
__device__ __half g_h1buf[2][Bsz * Hs];          // layer-1 hidden
__device__ __half g_xh[(size_t)Bsz * Tt * Din];  // x fp16
__device__ __half g_w0h[(size_t)G4 * Din];       // Wih0 fp16
__device__ unsigned g_barcnt;
__device__ unsigned g_bargen;

// ---------------------------------------------------------------- helpers
__device__ __forceinline__ void mma_f16(float* d, const unsigned* a, unsigned b0, unsigned b1) {
    asm volatile(
        "mma.sync.aligned.m16n8k16.row.col.f32.f16.f16.f32 "
        "{%0,%1,%2,%3},{%4,%5,%6,%7},{%8,%9},{%0,%1,%2,%3};"
        : "+f"(d[0]), "+f"(d[1]), "+f"(d[2]), "+f"(d[3])
        : "r"(a[0]), "r"(a[1]), "r"(a[2]), "r"(a[3]), "r"(b0), "r"(b1));
}

__device__ __forceinline__ void cp16(unsigned saddr, const void* g) {
    asm volatile("cp.async.cg.shared.global [%0], [%1], 16;" :: "r"(saddr), "l"(g));
}

__device__ __forceinline__ float sigmoidf_(float x) {
    return 1.f / (1.f + expf(-x));
}

__device__ __forceinline__ void grid_barrier(unsigned nblk) {
    __syncthreads();
    if (threadIdx.x == 0) {
        asm volatile("fence.acq_rel.gpu;" ::: "memory");
        unsigned gen;
        asm volatile("ld.relaxed.gpu.global.u32 %0, [%1];" : "=r"(gen) : "l"(&g_bargen));
        if (atomicAdd(&g_barcnt, 1u) == nblk - 1u) {
            g_barcnt = 0;
            asm volatile("st.release.gpu.global.u32 [%0], %1;" :: "l"(&g_bargen), "r"(gen + 1u) : "memory");
        } else {
            unsigned cur;
            do {
                asm volatile("ld.acquire.gpu.global.u32 %0, [%1];" : "=r"(cur) : "l"(&g_bargen) : "memory");
            } while (cur == gen);
        }
    }
    __syncthreads();
}

// ---------------------------------------------------------------- fp32 -> fp16
__global__ void tohalf_kernel(const float* __restrict__ src, __half* __restrict__ dst, int n)
{
    for (int i = blockIdx.x * blockDim.x + threadIdx.x; i < n; i += gridDim.x * blockDim.x)
        dst[i] = __float2half_rn(src[i]);
}

// ---------------------------------------------------------------- xg0 GEMM (fp16 in/out)
#define GSMEM (GS * STAGEH * 2 * 2)

__global__ __launch_bounds__(256, 2)
void gemm_xg_kernel(const __half* __restrict__ A, const __half* __restrict__ W,
                    const float* __restrict__ bias, int K)
{
    extern __shared__ __half gsm[];
    __half* As = gsm;
    __half* Bs = gsm + GS * STAGEH;

    const int tid  = threadIdx.x;
    const int lane = tid & 31, warp = tid >> 5;
    const int gid  = lane >> 2, tig = lane & 3;
    const int wm   = warp >> 1, wn = warp & 1;
    const int bm   = blockIdx.y * 128, bn = blockIdx.x * 128;

    const __half* ga[2]; const __half* gb[2]; int soff[2];
    #pragma unroll
    for (int j = 0; j < 2; ++j) {
        int i = tid + j * 256;
        int row = i >> 2, seg = (i & 3) * 8;
        int rm = bm + row;
        ga[j] = A + ((size_t)(rm & 63) * Tt + (rm >> 6)) * Din + seg;
        gb[j] = W + (size_t)(bn + row) * K + seg;
        soff[j] = row * GSTRIDE + seg;
    }
    unsigned sA = (unsigned)__cvta_generic_to_shared(As);
    unsigned sB = (unsigned)__cvta_generic_to_shared(Bs);

    const int nch = K / 32;

    auto stage = [&](int s, int k0) {
        #pragma unroll
        for (int j = 0; j < 2; ++j) {
            cp16(sA + (s * STAGEH + soff[j]) * 2, ga[j] + k0);
            cp16(sB + (s * STAGEH + soff[j]) * 2, gb[j] + k0);
        }
        asm volatile("cp.async.commit_group;");
    };

    stage(0, 0);
    stage(1, 32);

    float acc[2][8][4] = {};

    for (int c = 0; c < nch; ++c) {
        if (c + 1 < nch) asm volatile("cp.async.wait_group 1;");
        else             asm volatile("cp.async.wait_group 0;");
        __syncthreads();
        if (c + 2 < nch) stage((c + 2) % GS, (c + 2) * 32);

        const __half* Asl = As + (c % GS) * STAGEH;
        const __half* Bsl = Bs + (c % GS) * STAGEH;
        #pragma unroll
        for (int s = 0; s < 2; ++s) {
            int kk = s * 16;
            unsigned a[2][4];
            #pragma unroll
            for (int mt = 0; mt < 2; ++mt) {
                int m = wm * 32 + mt * 16 + gid;
                a[mt][0] = *(const unsigned*)&Asl[m * GSTRIDE + kk + 2 * tig];
                a[mt][1] = *(const unsigned*)&Asl[(m + 8) * GSTRIDE + kk + 2 * tig];
                a[mt][2] = *(const unsigned*)&Asl[m * GSTRIDE + kk + 8 + 2 * tig];
                a[mt][3] = *(const unsigned*)&Asl[(m + 8) * GSTRIDE + kk + 8 + 2 * tig];
            }
            #pragma unroll
            for (int nt = 0; nt < 8; ++nt) {
                int n = wn * 64 + nt * 8 + gid;
                unsigned b0 = *(const unsigned*)&Bsl[n * GSTRIDE + kk + 2 * tig];
                unsigned b1 = *(const unsigned*)&Bsl[n * GSTRIDE + kk + 8 + 2 * tig];
                mma_f16(acc[0][nt], a[0], b0, b1);
                mma_f16(acc[1][nt], a[1], b0, b1);
            }
        }
    }

    #pragma unroll
    for (int mt = 0; mt < 2; ++mt) {
        #pragma unroll
        for (int nt = 0; nt < 8; ++nt) {
            int row = bm + wm * 32 + mt * 16 + gid;
            int col = bn + wn * 64 + nt * 8 + 2 * tig;
            float bc0 = bias[col], bc1 = bias[col + 1];
            *reinterpret_cast<__half2*>(&g_xgh[(size_t)row * G4 + col]) =
                __floats2half2_rn(acc[mt][nt][0] + bc0, acc[mt][nt][1] + bc1);
            *reinterpret_cast<__half2*>(&g_xgh[(size_t)(row + 8) * G4 + col]) =
                __floats2half2_rn(acc[mt][nt][2] + bc0, acc[mt][nt][3] + bc1);
        }
    }
}

// ---------------------------------------------------------------- fused 2-layer recurrence
// 128 persistent CTAs, each owns units u0..u0+7 of BOTH layers.
// Step s: warps 0-3 (L0): load h0[s-1] frags, MMA vs Whh0 (h0[s] gates) AND vs
// Wih1 (L1 input gates -> smem red). warps 4-7 (L1): load h1[s-2] frags, MMA vs
// Whh1; add red + b1 -> h1[s-1]. One grid barrier per step; c-state in registers.
#define WS0 0
#define WS1 (32*WSROW)
#define WS2 (64*WSROW)
#define RSMEM (96*WSROW*2 + 64*REDSTRIDE*4)

__global__ __launch_bounds__(256, 1)
void rec2_kernel(const float* __restrict__ Whh0, const float* __restrict__ Wih1,
                 const float* __restrict__ Whh1, const float* __restrict__ b1)
{
    extern __shared__ unsigned char smraw[];
    __half* Ws = (__half*)smraw;                       // [96][WSROW]
    float* red = (float*)(smraw + 96 * WSROW * 2);     // [64][34]

    const int tid  = threadIdx.x;
    const int lane = tid & 31, warp = tid >> 5;
    const int gid  = lane >> 2, tig = lane & 3;
    const int u0   = blockIdx.x * 8;
    const bool isL0 = warp < 4;
    const int mrow = (warp & 3) * 16;

    // one-time: 3 weight slices (rows g*Hs + u0 + n) -> smem fp16
    for (int l = 0; l < 32; ++l) {
        int g = l >> 3, n = l & 7;
        const float* s0 = Whh0 + (size_t)(g * Hs + u0 + n) * Hs;
        const float* s1 = Wih1 + (size_t)(g * Hs + u0 + n) * Hs;
        const float* s2 = Whh1 + (size_t)(g * Hs + u0 + n) * Hs;
        for (int k = tid; k < Hs; k += 256) {
            Ws[WS0 + l * WSROW + k] = __float2half_rn(s0[k]);
            Ws[WS1 + l * WSROW + k] = __float2half_rn(s1[k]);
            Ws[WS2 + l * WSROW + k] = __float2half_rn(s2[k]);
        }
    }
    // zero the h "minus-one" parity buffers for this CTA's units
    for (int i = tid; i < 512; i += 256) {
        int b = i >> 3, u = i & 7;
        g_h0buf[1][b * Hs + u0 + u] = __float2half_rn(0.f);
        g_h1buf[1][b * Hs + u0 + u] = __float2half_rn(0.f);
    }

    // per-thread cell state (4 cells: rows {rA,rB} x units {v0,v0+1})
    float c0[4] = {0.f, 0.f, 0.f, 0.f};   // layer-0 cells (L0 warps)
    float c1[4] = {0.f, 0.f, 0.f, 0.f};   // layer-1 cells (L1 warps)
    const int rA = mrow + gid, rB = rA + 8;
    const int v0 = u0 + 2 * tig;

    // L1 bias, preloaded
    float bi1[4][2];
    #pragma unroll
    for (int g = 0; g < 4; ++g) {
        bi1[g][0] = b1[g * Hs + v0];
        bi1[g][1] = b1[g * Hs + v0 + 1];
    }

    grid_barrier(NBLK_REC);

    for (int s = 0; s <= Tt; ++s) {
        if (isL0) {
            // ---------------- layer-0 + layer-1-input warps ----------------
            const __half* hp = g_h0buf[(s + 1) & 1];   // h0[s-1]
            // prefetch xg0[t=s]
            __half2 px[8];
            if (s < Tt) {
                const __half* xb = g_xgh + ((size_t)s * Bsz) * G4 + v0;
                #pragma unroll
                for (int g = 0; g < 4; ++g) {
                    px[g]     = *(const __half2*)(xb + (size_t)rA * G4 + g * Hs);
                    px[4 + g] = *(const __half2*)(xb + (size_t)rB * G4 + g * Hs);
                }
            }

            float acc0[4][4] = {};   // vs Whh0
            float acc1[4][4] = {};   // vs Wih1
            const __half* hr0 = hp + rA * Hs + 2 * tig;
            const __half* hr1 = hr0 + 8 * Hs;

            #pragma unroll 8
            for (int ks = 0; ks < 64; ++ks) {
                int k16 = ks * 16;
                unsigned a[4];
                a[0] = *(const unsigned*)(hr0 + k16);
                a[1] = *(const unsigned*)(hr1 + k16);
                a[2] = *(const unsigned*)(hr0 + k16 + 8);
                a[3] = *(const unsigned*)(hr1 + k16 + 8);
                int kw = k16 + 2 * tig;
                #pragma unroll
                for (int g = 0; g < 4; ++g) {
                    const __half* w0 = Ws + WS0 + (g * 8 + gid) * WSROW + kw;
                    mma_f16(acc0[g], a, *(const unsigned*)w0, *(const unsigned*)(w0 + 8));
                    const __half* w1 = Ws + WS1 + (g * 8 + gid) * WSROW + kw;
                    mma_f16(acc1[g], a, *(const unsigned*)w1, *(const unsigned*)(w1 + 8));
                }
            }

            // hand L1-input partials to L1 warps
            #pragma unroll
            for (int g = 0; g < 4; ++g) {
                float* r0 = red + rA * REDSTRIDE + g * 8 + 2 * tig;
                *reinterpret_cast<float2*>(r0) = make_float2(acc1[g][0], acc1[g][1]);
                *reinterpret_cast<float2*>(r0 + 8 * REDSTRIDE) = make_float2(acc1[g][2], acc1[g][3]);
            }
            __syncthreads();

            if (s < Tt) {
                __half* hn = g_h0buf[s & 1];
                // 4 cells: j=0:(rA,v0) 1:(rA,v1) 2:(rB,v0) 3:(rB,v1)
                float hv[4];
                #pragma unroll
                for (int j = 0; j < 4; ++j) {
                    int fr = j >> 1, fc = j & 1;           // frag row sel, col sel
                    float gi = acc0[0][fr * 2 + fc] + __half2float(fc ? __high2half(px[fr * 4]) : __low2half(px[fr * 4]));
                    float gf = acc0[1][fr * 2 + fc] + __half2float(fc ? __high2half(px[fr * 4 + 1]) : __low2half(px[fr * 4 + 1]));
                    float gg = acc0[2][fr * 2 + fc] + __half2float(fc ? __high2half(px[fr * 4 + 2]) : __low2half(px[fr * 4 + 2]));
                    float go = acc0[3][fr * 2 + fc] + __half2float(fc ? __high2half(px[fr * 4 + 3]) : __low2half(px[fr * 4 + 3]));
                    gi = sigmoidf_(gi); gf = sigmoidf_(gf);
                    gg = tanhf(gg);     go = sigmoidf_(go);
                    float c = gf * c0[j] + gi * gg;
                    c0[j] = c;
                    hv[j] = go * tanhf(c);
                }
                *reinterpret_cast<__half2*>(hn + rA * Hs + v0) = __floats2half2_rn(hv[0], hv[1]);
                *reinterpret_cast<__half2*>(hn + rB * Hs + v0) = __floats2half2_rn(hv[2], hv[3]);
            }
        } else {
            // ---------------- layer-1 recurrent warps ----------------
            const __half* hp = g_h1buf[s & 1];          // h1[s-2]
            float accr[4][4] = {};
            const __half* hr0 = hp + rA * Hs + 2 * tig;
            const __half* hr1 = hr0 + 8 * Hs;

            #pragma unroll 8
            for (int ks = 0; ks < 64; ++ks) {
                int k16 = ks * 16;
                unsigned a[4];
                a[0] = *(const unsigned*)(hr0 + k16);
                a[1] = *(const unsigned*)(hr1 + k16);
                a[2] = *(const unsigned*)(hr0 + k16 + 8);
                a[3] = *(const unsigned*)(hr1 + k16 + 8);
                int kw = k16 + 2 * tig;
                #pragma unroll
                for (int g = 0; g < 4; ++g) {
                    const __half* w2 = Ws + WS2 + (g * 8 + gid) * WSROW + kw;
                    mma_f16(accr[g], a, *(const unsigned*)w2, *(const unsigned*)(w2 + 8));
                }
            }
            __syncthreads();   // wait for red from L0 warps

            if (s >= 1) {
                __half* hn = g_h1buf[(s + 1) & 1];      // h1[s-1]
                float hv[4];
                #pragma unroll
                for (int j = 0; j < 4; ++j) {
                    int fr = j >> 1, fc = j & 1;
                    int rr = fr ? rB : rA;
                    const float* rd = red + rr * REDSTRIDE + 2 * tig + fc;
                    float gi = accr[0][fr * 2 + fc] + rd[0]  + bi1[0][fc];
                    float gf = accr[1][fr * 2 + fc] + rd[8]  + bi1[1][fc];
                    float gg = accr[2][fr * 2 + fc] + rd[16] + bi1[2][fc];
                    float go = accr[3][fr * 2 + fc] + rd[24] + bi1[3][fc];
                    gi = sigmoidf_(gi); gf = sigmoidf_(gf);
                    gg = tanhf(gg);     go = sigmoidf_(go);
                    float c = gf * c1[j] + gi * gg;
                    c1[j] = c;
                    hv[j] = go * tanhf(c);
                }
                *reinterpret_cast<__half2*>(hn + rA * Hs + v0) = __floats2half2_rn(hv[0], hv[1]);
                *reinterpret_cast<__half2*>(hn + rB * Hs + v0) = __floats2half2_rn(hv[2], hv[3]);
            }
        }
        grid_barrier(NBLK_REC);
    }
}

// ---------------------------------------------------------------- final FC
__global__ void fc_kernel(const float* __restrict__ Wfc, const float* __restrict__ bfc,
                          float* __restrict__ out)
{
    int b = blockIdx.x;
    const __half* h = g_h1buf[1] + b * Hs;   // h1[511] lives in parity buffer 1
    float s = 0.f;
    for (int k = threadIdx.x; k < Hs; k += 128)
        s += __half2float(h[k]) * Wfc[k];
    #pragma unroll
    for (int o = 16; o > 0; o >>= 1)
        s += __shfl_down_sync(0xffffffffu, s, o);
    __shared__ float sm[4];
    if ((threadIdx.x & 31) == 0) sm[threadIdx.x >> 5] = s;
    __syncthreads();
    if (threadIdx.x == 0)
        out[b] = sm[0] + sm[1] + sm[2] + sm[3] + bfc[0];
}

// ---------------------------------------------------------------- launch
extern "C" void kernel_launch(void* const* d_in, const int* in_sizes, int n_in,
                              void* d_out, int out_size)
{
    (void)in_sizes; (void)n_in; (void)out_size;
    const float* x    = (const float*)d_in[0];
    const float* Wih0 = (const float*)d_in[1];
    const float* Whh0 = (const float*)d_in[2];
    const float* b0   = (const float*)d_in[3];
    const float* Wih1 = (const float*)d_in[4];
    const float* Whh1 = (const float*)d_in[5];
    const float* b1   = (const float*)d_in[6];
    const float* Wfc  = (const float*)d_in[7];
    const float* bfc  = (const float*)d_in[8];
    float* out = (float*)d_out;

    cudaFuncSetAttribute(rec2_kernel, cudaFuncAttributeMaxDynamicSharedMemorySize, RSMEM);
    cudaFuncSetAttribute(gemm_xg_kernel, cudaFuncAttributeMaxDynamicSharedMemorySize, GSMEM);

    __half* xh  = nullptr; cudaGetSymbolAddress((void**)&xh,  g_xh);
    __half* w0h = nullptr; cudaGetSymbolAddress((void**)&w0h, g_w0h);

    tohalf_kernel<<<4096, 256>>>(x,    xh,  Bsz * Tt * Din);
    tohalf_kernel<<<1024, 256>>>(Wih0, w0h, G4 * Din);

    dim3 grid(G4 / 128, MROWS / 128);   // (32, 256)
    gemm_xg_kernel<<<grid, 256, GSMEM>>>(xh, w0h, b0, Din);
    rec2_kernel<<<NBLK_REC, 256, RSMEM>>>(Whh0, Wih1, Whh1, b1);
    fc_kernel<<<Bsz, 128>>>(Wfc, bfc, out);
}

// round 6
// speedup vs baseline: 2.7834x; 1.2813x over previous
#include <cuda_runtime.h>
#include <cuda_fp16.h>
#include <cstdint>
#include <math.h>

#define Bsz 64
#define Tt  512
#define Din 256
#define Hs  1024
#define G4  4096
#define MROWS (Tt*Bsz)
#define NBLK_REC 128
#define WSROW 1032              // weight smem row stride (halves); 2064B: 16B-aligned, bank-staggered
#define REDSTRIDE 34
#define GS 3
#define GSTRIDE 40
#define STAGEH (128*GSTRIDE)
#define RTHREADS 384

// persistent scratch
__device__ __half g_xgh[(size_t)MROWS * G4];     // [T][B][4H] layer-0 input gates
__device__ __half g_h0buf[2][Bsz * Hs];          // layer-0 hidden (permuted cols)
__device__ __half g_h1buf[2][Bsz * Hs];          // layer-1 hidden (permuted cols)
__device__ __half g_xh[(size_t)Bsz * Tt * Din];
__device__ __half g_w0h[(size_t)G4 * Din];
__device__ unsigned g_barcnt;
__device__ unsigned g_bargen;

// ---------------------------------------------------------------- helpers
__device__ __forceinline__ void mma_f16(float* d, const unsigned* a, unsigned b0, unsigned b1) {
    asm volatile(
        "mma.sync.aligned.m16n8k16.row.col.f32.f16.f16.f32 "
        "{%0,%1,%2,%3},{%4,%5,%6,%7},{%8,%9},{%0,%1,%2,%3};"
        : "+f"(d[0]), "+f"(d[1]), "+f"(d[2]), "+f"(d[3])
        : "r"(a[0]), "r"(a[1]), "r"(a[2]), "r"(a[3]), "r"(b0), "r"(b1));
}

__device__ __forceinline__ void cp16(unsigned saddr, const void* g) {
    asm volatile("cp.async.cg.shared.global [%0], [%1], 16;" :: "r"(saddr), "l"(g));
}

// col-permutation within each 16-col block: {2t,2t+1,8+2t,8+2t+1} -> {4t,4t+1,4t+2,4t+3}
__device__ __forceinline__ int perm16(int c) {
    return (c < 8) ? ((c >> 1) * 4 + (c & 1)) : (((c - 8) >> 1) * 4 + 2 + (c & 1));
}

__device__ __forceinline__ float sigf(float x)  { return __fdividef(1.f, 1.f + __expf(-x)); }
__device__ __forceinline__ float tanhf_(float x){ return __fdividef(2.f, 1.f + __expf(-2.f * x)) - 1.f; }

__device__ __forceinline__ void grid_barrier(unsigned nblk) {
    __syncthreads();
    if (threadIdx.x == 0) {
        asm volatile("fence.acq_rel.gpu;" ::: "memory");
        unsigned gen;
        asm volatile("ld.relaxed.gpu.global.u32 %0, [%1];" : "=r"(gen) : "l"(&g_bargen));
        if (atomicAdd(&g_barcnt, 1u) == nblk - 1u) {
            g_barcnt = 0;
            asm volatile("st.release.gpu.global.u32 [%0], %1;" :: "l"(&g_bargen), "r"(gen + 1u) : "memory");
        } else {
            unsigned cur;
            do {
                asm volatile("ld.acquire.gpu.global.u32 %0, [%1];" : "=r"(cur) : "l"(&g_bargen) : "memory");
            } while (cur == gen);
        }
    }
    __syncthreads();
}

// ---------------------------------------------------------------- fp32 -> fp16
__global__ void tohalf_kernel(const float* __restrict__ src, __half* __restrict__ dst, int n)
{
    for (int i = blockIdx.x * blockDim.x + threadIdx.x; i < n; i += gridDim.x * blockDim.x)
        dst[i] = __float2half_rn(src[i]);
}

// ---------------------------------------------------------------- xg0 GEMM
#define GSMEM (GS * STAGEH * 2 * 2)

__global__ __launch_bounds__(256, 2)
void gemm_xg_kernel(const __half* __restrict__ A, const __half* __restrict__ W,
                    const float* __restrict__ bias, int K)
{
    extern __shared__ __half gsm[];
    __half* As = gsm;
    __half* Bs = gsm + GS * STAGEH;

    const int tid  = threadIdx.x;
    const int lane = tid & 31, warp = tid >> 5;
    const int gid  = lane >> 2, tig = lane & 3;
    const int wm   = warp >> 1, wn = warp & 1;
    const int bm   = blockIdx.y * 128, bn = blockIdx.x * 128;

    const __half* ga[2]; const __half* gb[2]; int soff[2];
    #pragma unroll
    for (int j = 0; j < 2; ++j) {
        int i = tid + j * 256;
        int row = i >> 2, seg = (i & 3) * 8;
        int rm = bm + row;
        ga[j] = A + ((size_t)(rm & 63) * Tt + (rm >> 6)) * Din + seg;
        gb[j] = W + (size_t)(bn + row) * K + seg;
        soff[j] = row * GSTRIDE + seg;
    }
    unsigned sA = (unsigned)__cvta_generic_to_shared(As);
    unsigned sB = (unsigned)__cvta_generic_to_shared(Bs);

    const int nch = K / 32;

    auto stage = [&](int s, int k0) {
        #pragma unroll
        for (int j = 0; j < 2; ++j) {
            cp16(sA + (s * STAGEH + soff[j]) * 2, ga[j] + k0);
            cp16(sB + (s * STAGEH + soff[j]) * 2, gb[j] + k0);
        }
        asm volatile("cp.async.commit_group;");
    };

    stage(0, 0);
    stage(1, 32);

    float acc[2][8][4] = {};

    for (int c = 0; c < nch; ++c) {
        if (c + 1 < nch) asm volatile("cp.async.wait_group 1;");
        else             asm volatile("cp.async.wait_group 0;");
        __syncthreads();
        if (c + 2 < nch) stage((c + 2) % GS, (c + 2) * 32);

        const __half* Asl = As + (c % GS) * STAGEH;
        const __half* Bsl = Bs + (c % GS) * STAGEH;
        #pragma unroll
        for (int s = 0; s < 2; ++s) {
            int kk = s * 16;
            unsigned a[2][4];
            #pragma unroll
            for (int mt = 0; mt < 2; ++mt) {
                int m = wm * 32 + mt * 16 + gid;
                a[mt][0] = *(const unsigned*)&Asl[m * GSTRIDE + kk + 2 * tig];
                a[mt][1] = *(const unsigned*)&Asl[(m + 8) * GSTRIDE + kk + 2 * tig];
                a[mt][2] = *(const unsigned*)&Asl[m * GSTRIDE + kk + 8 + 2 * tig];
                a[mt][3] = *(const unsigned*)&Asl[(m + 8) * GSTRIDE + kk + 8 + 2 * tig];
            }
            #pragma unroll
            for (int nt = 0; nt < 8; ++nt) {
                int n = wn * 64 + nt * 8 + gid;
                unsigned b0 = *(const unsigned*)&Bsl[n * GSTRIDE + kk + 2 * tig];
                unsigned b1 = *(const unsigned*)&Bsl[n * GSTRIDE + kk + 8 + 2 * tig];
                mma_f16(acc[0][nt], a[0], b0, b1);
                mma_f16(acc[1][nt], a[1], b0, b1);
            }
        }
    }

    #pragma unroll
    for (int mt = 0; mt < 2; ++mt) {
        #pragma unroll
        for (int nt = 0; nt < 8; ++nt) {
            int row = bm + wm * 32 + mt * 16 + gid;
            int col = bn + wn * 64 + nt * 8 + 2 * tig;
            float bc0 = bias[col], bc1 = bias[col + 1];
            *reinterpret_cast<__half2*>(&g_xgh[(size_t)row * G4 + col]) =
                __floats2half2_rn(acc[mt][nt][0] + bc0, acc[mt][nt][1] + bc1);
            *reinterpret_cast<__half2*>(&g_xgh[(size_t)(row + 8) * G4 + col]) =
                __floats2half2_rn(acc[mt][nt][2] + bc0, acc[mt][nt][3] + bc1);
        }
    }
}

// ---------------------------------------------------------------- fused 2-layer recurrence
// 384 threads = 3 warp-groups of 4 warps: grp0 Whh0 (h0), grp1 Wih1 (h0 -> red),
// grp2 Whh1 (h1, consumes LAST step's red). One grid barrier per step; no mid sync.
#define RSMEM (96*WSROW*2 + 2*64*REDSTRIDE*4)

__global__ __launch_bounds__(RTHREADS, 1)
void rec2_kernel(const float* __restrict__ Whh0, const float* __restrict__ Wih1,
                 const float* __restrict__ Whh1, const float* __restrict__ b1)
{
    extern __shared__ unsigned char smraw[];
    __half* Ws  = (__half*)smraw;                         // [3][32][WSROW]
    float* redb = (float*)(smraw + 96 * WSROW * 2);       // [2][64][REDSTRIDE]

    const int tid  = threadIdx.x;
    const int lane = tid & 31, warp = tid >> 5;
    const int gid  = lane >> 2, tig = lane & 3;
    const int grp  = warp >> 2;          // 0,1,2
    const int mt   = warp & 3;
    const int u0   = blockIdx.x * 8;
    const int rA   = mt * 16 + gid, rB = rA + 8;

    // one-time: 3 weight slices -> smem fp16
    {
        const float* srcs[3] = {Whh0, Wih1, Whh1};
        for (int sl = 0; sl < 3; ++sl) {
            const float* src = srcs[sl];
            __half* dst = Ws + sl * 32 * WSROW;
            for (int i = tid; i < 32 * Hs; i += RTHREADS) {
                int l = i >> 10, k = i & 1023;
                int g = l >> 3, n = l & 7;
                dst[l * WSROW + k] = __float2half_rn(src[(size_t)(g * Hs + u0 + n) * Hs + k]);
            }
        }
    }
    // zero parity-1 h buffers at this CTA's permuted columns
    for (int i = tid; i < 512; i += RTHREADS) {
        int b = i >> 3, u = i & 7;
        int col = (u0 & ~15) + perm16((u0 + u) & 15);
        g_h0buf[1][b * Hs + col] = __float2half_rn(0.f);
        g_h1buf[1][b * Hs + col] = __float2half_rn(0.f);
    }

    // ldmatrix lane pointers (x4: tiles = gate 2p+(lane>>4), k-half (lane>>3)&1, row lane&7)
    const int ltile = lane >> 3, lrow = lane & 7;
    unsigned lp0, lp1;
    {
        const __half* wsl = Ws + grp * 32 * WSROW;
        const __half* p0 = wsl + (size_t)(((ltile >> 1)) * 8 + lrow) * WSROW + (ltile & 1) * 8;
        const __half* p1 = wsl + (size_t)((2 + (ltile >> 1)) * 8 + lrow) * WSROW + (ltile & 1) * 8;
        lp0 = (unsigned)__cvta_generic_to_shared(p0);
        lp1 = (unsigned)__cvta_generic_to_shared(p1);
    }

    float cst[4] = {0.f, 0.f, 0.f, 0.f};
    float bi1[4][2];
    if (grp == 2) {
        #pragma unroll
        for (int g = 0; g < 4; ++g) {
            bi1[g][0] = b1[g * Hs + u0 + 2 * tig];
            bi1[g][1] = b1[g * Hs + u0 + 2 * tig + 1];
        }
    }
    const int wcol = (u0 & ~15) + 4 * tig + ((u0 & 8) ? 2 : 0);   // permuted write col

    grid_barrier(NBLK_REC);

    for (int s = 0; s <= Tt + 1; ++s) {
        // xg prefetch (grp0 only)
        __half2 px[8];
        if (grp == 0 && s < Tt) {
            const __half* xb = g_xgh + ((size_t)s * Bsz) * G4 + u0 + 2 * tig;
            #pragma unroll
            for (int g = 0; g < 4; ++g) {
                px[g]     = *(const __half2*)(xb + (size_t)rA * G4 + g * Hs);
                px[4 + g] = *(const __half2*)(xb + (size_t)rB * G4 + g * Hs);
            }
        }

        const bool doM = (grp == 0) ? (s < Tt) : (grp == 1) ? (s <= Tt) : (s >= 2);
        float acc[4][4] = {};

        if (doM) {
            const __half* hp = (grp == 2) ? g_h1buf[(s + 1) & 1] : g_h0buf[(s + 1) & 1];
            const uint2* aA = (const uint2*)(hp + (size_t)rA * Hs) + tig;
            const uint2* aB = (const uint2*)(hp + (size_t)rB * Hs) + tig;
            #pragma unroll 8
            for (int ks = 0; ks < 64; ++ks) {
                uint2 vA = aA[4 * ks], vB = aB[4 * ks];
                unsigned a[4] = {vA.x, vB.x, vA.y, vB.y};
                unsigned b0, b1r, b2, b3;
                asm volatile("ldmatrix.sync.aligned.m8n8.x4.shared.b16 {%0,%1,%2,%3}, [%4];"
                             : "=r"(b0), "=r"(b1r), "=r"(b2), "=r"(b3) : "r"(lp0 + ks * 32));
                mma_f16(acc[0], a, b0, b1r);
                mma_f16(acc[1], a, b2, b3);
                asm volatile("ldmatrix.sync.aligned.m8n8.x4.shared.b16 {%0,%1,%2,%3}, [%4];"
                             : "=r"(b0), "=r"(b1r), "=r"(b2), "=r"(b3) : "r"(lp1 + ks * 32));
                mma_f16(acc[2], a, b0, b1r);
                mma_f16(acc[3], a, b2, b3);
            }
        }

        if (grp == 1) {
            if (s <= Tt) {
                float* rc = redb + (s & 1) * 64 * REDSTRIDE;
                #pragma unroll
                for (int g = 0; g < 4; ++g) {
                    float* r0 = rc + rA * REDSTRIDE + g * 8 + 2 * tig;
                    *reinterpret_cast<float2*>(r0) = make_float2(acc[g][0], acc[g][1]);
                    *reinterpret_cast<float2*>(r0 + 8 * REDSTRIDE) = make_float2(acc[g][2], acc[g][3]);
                }
            }
        } else if (grp == 0) {
            if (s < Tt) {
                __half* hn = g_h0buf[s & 1];
                float hv[4];
                #pragma unroll
                for (int j = 0; j < 4; ++j) {
                    int fr = j >> 1, fc = j & 1;
                    float gi = acc[0][fr * 2 + fc] + (fc ? __high2float(px[fr * 4 + 0]) : __low2float(px[fr * 4 + 0]));
                    float gf = acc[1][fr * 2 + fc] + (fc ? __high2float(px[fr * 4 + 1]) : __low2float(px[fr * 4 + 1]));
                    float gg = acc[2][fr * 2 + fc] + (fc ? __high2float(px[fr * 4 + 2]) : __low2float(px[fr * 4 + 2]));
                    float go = acc[3][fr * 2 + fc] + (fc ? __high2float(px[fr * 4 + 3]) : __low2float(px[fr * 4 + 3]));
                    gi = sigf(gi); gf = sigf(gf); gg = tanhf_(gg); go = sigf(go);
                    float c = gf * cst[j] + gi * gg;
                    cst[j] = c;
                    hv[j] = go * tanhf_(c);
                }
                *reinterpret_cast<__half2*>(hn + (size_t)rA * Hs + wcol) = __floats2half2_rn(hv[0], hv[1]);
                *reinterpret_cast<__half2*>(hn + (size_t)rB * Hs + wcol) = __floats2half2_rn(hv[2], hv[3]);
            }
        } else {
            if (s >= 2) {
                const float* rp = redb + ((s - 1) & 1) * 64 * REDSTRIDE;
                __half* hn = g_h1buf[s & 1];
                float hv[4];
                #pragma unroll
                for (int j = 0; j < 4; ++j) {
                    int fr = j >> 1, fc = j & 1;
                    int rr = fr ? rB : rA;
                    const float* rd = rp + rr * REDSTRIDE + 2 * tig + fc;
                    float gi = acc[0][fr * 2 + fc] + rd[0]  + bi1[0][fc];
                    float gf = acc[1][fr * 2 + fc] + rd[8]  + bi1[1][fc];
                    float gg = acc[2][fr * 2 + fc] + rd[16] + bi1[2][fc];
                    float go = acc[3][fr * 2 + fc] + rd[24] + bi1[3][fc];
                    gi = sigf(gi); gf = sigf(gf); gg = tanhf_(gg); go = sigf(go);
                    float c = gf * cst[j] + gi * gg;
                    cst[j] = c;
                    hv[j] = go * tanhf_(c);
                }
                *reinterpret_cast<__half2*>(hn + (size_t)rA * Hs + wcol) = __floats2half2_rn(hv[0], hv[1]);
                *reinterpret_cast<__half2*>(hn + (size_t)rB * Hs + wcol) = __floats2half2_rn(hv[2], hv[3]);
            }
        }
        if (s <= Tt) grid_barrier(NBLK_REC);
    }
}

// ---------------------------------------------------------------- final FC (permuted h)
__global__ void fc_kernel(const float* __restrict__ Wfc, const float* __restrict__ bfc,
                          float* __restrict__ out)
{
    int b = blockIdx.x;
    const __half* h = g_h1buf[1] + b * Hs;   // h1[511] written at s=513 -> parity 1
    float s = 0.f;
    for (int k = threadIdx.x; k < Hs; k += 128) {
        int col = (k & ~15) + perm16(k & 15);
        s += __half2float(h[col]) * Wfc[k];
    }
    #pragma unroll
    for (int o = 16; o > 0; o >>= 1)
        s += __shfl_down_sync(0xffffffffu, s, o);
    __shared__ float sm[4];
    if ((threadIdx.x & 31) == 0) sm[threadIdx.x >> 5] = s;
    __syncthreads();
    if (threadIdx.x == 0)
        out[b] = sm[0] + sm[1] + sm[2] + sm[3] + bfc[0];
}

// ---------------------------------------------------------------- launch
extern "C" void kernel_launch(void* const* d_in, const int* in_sizes, int n_in,
                              void* d_out, int out_size)
{
    (void)in_sizes; (void)n_in; (void)out_size;
    const float* x    = (const float*)d_in[0];
    const float* Wih0 = (const float*)d_in[1];
    const float* Whh0 = (const float*)d_in[2];
    const float* b0   = (const float*)d_in[3];
    const float* Wih1 = (const float*)d_in[4];
    const float* Whh1 = (const float*)d_in[5];
    const float* b1   = (const float*)d_in[6];
    const float* Wfc  = (const float*)d_in[7];
    const float* bfc  = (const float*)d_in[8];
    float* out = (float*)d_out;

    cudaFuncSetAttribute(rec2_kernel, cudaFuncAttributeMaxDynamicSharedMemorySize, RSMEM);
    cudaFuncSetAttribute(gemm_xg_kernel, cudaFuncAttributeMaxDynamicSharedMemorySize, GSMEM);

    __half* xh  = nullptr; cudaGetSymbolAddress((void**)&xh,  g_xh);
    __half* w0h = nullptr; cudaGetSymbolAddress((void**)&w0h, g_w0h);

    tohalf_kernel<<<4096, 256>>>(x,    xh,  Bsz * Tt * Din);
    tohalf_kernel<<<1024, 256>>>(Wih0, w0h, G4 * Din);

    dim3 grid(G4 / 128, MROWS / 128);
    gemm_xg_kernel<<<grid, 256, GSMEM>>>(xh, w0h, b0, Din);
    rec2_kernel<<<NBLK_REC, RTHREADS, RSMEM>>>(Whh0, Wih1, Whh1, b1);
    fc_kernel<<<Bsz, 128>>>(Wfc, bfc, out);
}